// round 10
// baseline (speedup 1.0000x reference)
#include <cuda_runtime.h>

#define N 131072
#define D 128
#define K 1024
#define NITERS 10
#define CHUNK 512
#define CHUNKS (N / CHUNK)   /* 256 */

// ---------------- persistent device scratch (no allocations allowed) ----------------
__device__ float g_centroids[K * D];
__device__ float g_csq[K];
__device__ float g_xsq[N];
__device__ int   g_assign[N];
__device__ int   g_rank[N];
__device__ int   g_order[N];
__device__ int   g_hist[CHUNKS * K];
__device__ int   g_counts_i[K];
__device__ int   g_offs[K];

// ---------------- assignment kernel: argmin_k ||x - c_k||^2 ----------------
// 512 threads (16 warps): tx = tid&15 over centroid pairs, ty = tid>>4 over points.
// Tile: 128 points x 1024 centroids in 8 chunks of 128.
// Per-thread micro-tile: 4 points x 8 centroids (4 adjacent pairs).
// X tile stored PRE-DUPLICATED as float2 {v,v} so the f32x2 'a' operand is a
// single broadcast LDS.64 (no mov.b64 packing). Every scalar fma chain is
// bit-identical to the passing round-9 kernel (ascending d, fma.rn).
#define CT_PITCH 130
#define XS2_FLOATS (128 * 128 * 2)                 /* float2[128][128] */
#define SMEM_FLOATS (XS2_FLOATS + 128 * CT_PITCH)
#define SMEM_BYTES (SMEM_FLOATS * 4)               /* 197632 B */

__global__ __launch_bounds__(512, 1)
void assign_kernel(const float* __restrict__ x) {
    extern __shared__ float sm[];
    float2* Xs2 = (float2*)sm;                 // [128 pts][128 d] duplicated
    float*  Ct  = sm + XS2_FLOATS;             // [128 d][CT_PITCH]

    const int tid = threadIdx.x;
    const int tx = tid & 15;
    const int ty = tid >> 4;                   // 0..31
    const int pBase = blockIdx.x * 128;

    // Load X tile (coalesced float4), store duplicated {v,v}.
    {
        const int r0 = tid >> 5, lane = tid & 31;
        #pragma unroll
        for (int s = 0; s < 8; s++) {
            const int p = r0 + s * 16;
            float4 v = *(const float4*)(x + (size_t)(pBase + p) * D + lane * 4);
            float2* dst = Xs2 + p * 128 + lane * 4;
            dst[0] = make_float2(v.x, v.x);
            dst[1] = make_float2(v.y, v.y);
            dst[2] = make_float2(v.z, v.z);
            dst[3] = make_float2(v.w, v.w);
        }
    }

    float xs[4];
    float bestv[4];
    int   besti[4];
    #pragma unroll
    for (int i = 0; i < 4; i++) {
        xs[i] = g_xsq[pBase + i * 32 + ty];
        bestv[i] = 3.4e38f;
        besti[i] = 0;
    }

    for (int chunk = 0; chunk < 8; chunk++) {
        const int c0 = chunk * 128;
        __syncthreads();  // protect Ct before overwrite
        // Load centroid chunk TRANSPOSED: Ct[d][cent]
        {
            const int r0 = tid >> 5, lane = tid & 31;
            #pragma unroll
            for (int s = 0; s < 8; s++) {
                const int c = r0 + s * 16;
                float4 v = *(const float4*)(g_centroids + (size_t)(c0 + c) * D + lane * 4);
                Ct[(lane * 4 + 0) * CT_PITCH + c] = v.x;
                Ct[(lane * 4 + 1) * CT_PITCH + c] = v.y;
                Ct[(lane * 4 + 2) * CT_PITCH + c] = v.z;
                Ct[(lane * 4 + 3) * CT_PITCH + c] = v.w;
            }
        }
        __syncthreads();

        unsigned long long acc[4][4];
        #pragma unroll
        for (int i = 0; i < 4; i++)
            #pragma unroll
            for (int j = 0; j < 4; j++) acc[i][j] = 0ull;

        #pragma unroll 4
        for (int d = 0; d < 128; d++) {
            unsigned long long b2[4];
            const float* crow = Ct + d * CT_PITCH + tx * 2;
            #pragma unroll
            for (int j = 0; j < 4; j++)
                b2[j] = *(const unsigned long long*)(crow + j * 32);
            #pragma unroll
            for (int i = 0; i < 4; i++) {
                const unsigned long long a2 =
                    *(const unsigned long long*)(Xs2 + (i * 32 + ty) * 128 + d);
                #pragma unroll
                for (int j = 0; j < 4; j++)
                    asm("fma.rn.f32x2 %0, %1, %2, %0;"
                        : "+l"(acc[i][j]) : "l"(a2), "l"(b2[j]));
            }
        }

        // Epilogue: d = xsq - 2*dot + csq ; running argmin (ascending c per thread)
        float cs0[4], cs1[4];
        int   cb[4];
        #pragma unroll
        for (int j = 0; j < 4; j++) {
            const int c = c0 + j * 32 + tx * 2;
            cb[j] = c;
            cs0[j] = g_csq[c];
            cs1[j] = g_csq[c + 1];
        }
        #pragma unroll
        for (int i = 0; i < 4; i++) {
            #pragma unroll
            for (int j = 0; j < 4; j++) {
                float v0, v1;
                asm("mov.b64 {%0, %1}, %2;" : "=f"(v0), "=f"(v1) : "l"(acc[i][j]));
                const float d0 = fmaf(-2.f, v0, xs[i]) + cs0[j];
                const float d1 = fmaf(-2.f, v1, xs[i]) + cs1[j];
                if (d0 < bestv[i]) { bestv[i] = d0; besti[i] = cb[j]; }
                if (d1 < bestv[i]) { bestv[i] = d1; besti[i] = cb[j] + 1; }
            }
        }
    }

    // Cross-thread argmin reduction over the 16 tx lanes per point (lex order).
    __syncthreads();
    float* rv = sm;                         // [128][16] floats
    int*   ri = (int*)(sm + 128 * 16);      // [128][16] ints
    #pragma unroll
    for (int i = 0; i < 4; i++) {
        const int p = i * 32 + ty;
        rv[p * 16 + tx] = bestv[i];
        ri[p * 16 + tx] = besti[i];
    }
    __syncthreads();
    if (tid < 128) {
        float bv = rv[tid * 16];
        int   bi = ri[tid * 16];
        #pragma unroll
        for (int t = 1; t < 16; t++) {
            const float v = rv[tid * 16 + t];
            const int  ix = ri[tid * 16 + t];
            if (v < bv || (v == bv && ix < bi)) { bv = v; bi = ix; }
        }
        g_assign[pBase + tid] = bi;
    }
}

// ---------------- deterministic stable counting-sort of points by cluster ----------------
__global__ __launch_bounds__(256)
void rank_kernel() {
    __shared__ int hist[8][K];
    const int warp = threadIdx.x >> 5;
    const int lane = threadIdx.x & 31;
    const int chunk = blockIdx.x * 8 + warp;
    int* h = hist[warp];
    for (int i = lane; i < K; i += 32) h[i] = 0;
    __syncwarp();
    const int base_n = chunk * CHUNK;
    for (int g = 0; g < CHUNK / 32; g++) {
        const int n = base_n + g * 32 + lane;
        const int a = g_assign[n];
        const unsigned mask = __match_any_sync(0xffffffffu, a);
        const int before = __popc(mask & ((1u << lane) - 1u));
        const int b = h[a];
        __syncwarp();
        g_rank[n] = b + before;
        if (lane == (int)(__ffs(mask) - 1)) h[a] = b + __popc(mask);
        __syncwarp();
    }
    for (int i = lane; i < K; i += 32) g_hist[chunk * K + i] = h[i];
}

__global__ void chunkscan_kernel() {
    const int k = blockIdx.x * blockDim.x + threadIdx.x;  // 0..K-1
    if (k >= K) return;
    int run = 0;
    for (int c = 0; c < CHUNKS; c++) {
        const int t = g_hist[c * K + k];
        g_hist[c * K + k] = run;
        run += t;
    }
    g_counts_i[k] = run;
}

__global__ void offs_kernel() {
    __shared__ int s[K];
    const int k = threadIdx.x;
    const int my = g_counts_i[k];
    s[k] = my;
    __syncthreads();
    for (int o = 1; o < K; o <<= 1) {
        const int t = (k >= o) ? s[k - o] : 0;
        __syncthreads();
        s[k] += t;
        __syncthreads();
    }
    g_offs[k] = s[k] - my;
}

__global__ void scatter_kernel() {
    const int n = blockIdx.x * blockDim.x + threadIdx.x;
    if (n >= N) return;
    const int a = g_assign[n];
    const int chunk = n / CHUNK;
    const int slot = g_offs[a] + g_hist[chunk * K + a] + g_rank[n];
    g_order[slot] = n;
}

// Update: fp32 serial fold, ADJACENT-PAIR-SWAPPED ascending order (FROZEN —
// this exact order matched golden), then plain fp32 divide (0/0 -> NaN).
__global__ __launch_bounds__(128)
void update_kernel(const float* __restrict__ x) {
    const int k = blockIdx.x;
    const int d = threadIdx.x;
    const int cnt = g_counts_i[k];
    const int off = g_offs[k];
    float s = 0.f;
    for (int j = 0; j < cnt; j++) {
        int jj = j ^ 1;
        if (jj >= cnt) jj = j;          // odd tail element stays in place
        const int n = g_order[off + jj];
        s += x[(size_t)n * D + d];
    }
    g_centroids[k * D + d] = s / (float)cnt;
}

// ---------------- support kernels ----------------
__global__ void init_centroids_kernel(const float* __restrict__ x) {
    const int i = blockIdx.x * blockDim.x + threadIdx.x;
    if (i < K * D) g_centroids[i] = x[i];  // c0 = x[:K]
}

__global__ void xsq_kernel(const float* __restrict__ x) {
    const int gtid = blockIdx.x * blockDim.x + threadIdx.x;
    const int w = gtid >> 5;
    const int lane = gtid & 31;
    if (w < N) {
        float4 v = *(const float4*)(x + (size_t)w * D + lane * 4);
        float s = v.x * v.x + v.y * v.y + v.z * v.z + v.w * v.w;
        #pragma unroll
        for (int o = 16; o; o >>= 1) s += __shfl_down_sync(0xffffffffu, s, o);
        if (lane == 0) g_xsq[w] = s;
    }
}

// csq: serial fma chain (FROZEN — form used in the golden-matching run).
__global__ void csq_kernel() {
    const int k = blockIdx.x * blockDim.x + threadIdx.x;
    if (k < K) {
        const float* c = g_centroids + (size_t)k * D;
        float s = 0.f;
        #pragma unroll 8
        for (int d = 0; d < D; d++) s = fmaf(c[d], c[d], s);
        g_csq[k] = s;
    }
}

// Output (float32): [clusters(131072), centroids(131072), counts(1024)]
__global__ void writeout_kernel(float* __restrict__ out, int out_size) {
    const int i = blockIdx.x * blockDim.x + threadIdx.x;
    if (i >= out_size) return;
    if (i < N) {
        out[i] = (float)g_assign[i];
    } else if (i < N + K * D) {
        out[i] = g_centroids[i - N];
    } else if (i < N + K * D + K) {
        out[i] = (float)g_counts_i[i - N - K * D];
    }
}

// ---------------- launch ----------------
extern "C" void kernel_launch(void* const* d_in, const int* in_sizes, int n_in,
                              void* d_out, int out_size) {
    const float* x = (const float*)d_in[0];
    float* out = (float*)d_out;

    cudaFuncSetAttribute(assign_kernel,
                         cudaFuncAttributeMaxDynamicSharedMemorySize, SMEM_BYTES);

    init_centroids_kernel<<<(K * D + 255) / 256, 256>>>(x);
    xsq_kernel<<<(N * 32 + 255) / 256, 256>>>(x);
    csq_kernel<<<(K + 255) / 256, 256>>>();

    for (int it = 0; it < NITERS; it++) {
        assign_kernel<<<N / 128, 512, SMEM_BYTES>>>(x);
        rank_kernel<<<CHUNKS / 8, 256>>>();
        chunkscan_kernel<<<(K + 255) / 256, 256>>>();
        offs_kernel<<<1, K>>>();
        scatter_kernel<<<(N + 255) / 256, 256>>>();
        update_kernel<<<K, 128>>>(x);
        csq_kernel<<<(K + 255) / 256, 256>>>();
    }
    writeout_kernel<<<(out_size + 255) / 256, 256>>>(out, out_size);
}

// round 11
// speedup vs baseline: 1.2144x; 1.2144x over previous
#include <cuda_runtime.h>

#define N 131072
#define D 128
#define K 1024
#define NITERS 10
#define CHUNK 512
#define CHUNKS (N / CHUNK)   /* 256 */

// ---------------- persistent device scratch (no allocations allowed) ----------------
__device__ float g_centroids[K * D];
__device__ float g_csq[K];
__device__ float g_xsq[N];
__device__ int   g_assign[N];
__device__ int   g_rank[N];
__device__ int   g_order[N];
__device__ int   g_hist[CHUNKS * K];
__device__ int   g_counts_i[K];
__device__ int   g_offs[K];

// ---------------- assignment kernel: argmin_k ||x - c_k||^2 ----------------
// 256 threads, 2 CTAs/SM (4 warps/SMSP). Per-thread micro-tile: 8 points x
// 8 centroids (4 adjacent pairs) — bit-identical fma chains to the passing R9
// kernel (scalar a LDS + mov.b64 dup + fma.rn.f32x2, ascending d).
// Centroid tile is processed in d-HALVES (64 d x 130) so smem/CTA = 97 KB,
// allowing 2 CTAs per SM for latency hiding. 1.0 B/MAC on the smem crossbar.
#define XS_PITCH 129
#define CTH_PITCH 130
#define XS_FLOATS (128 * XS_PITCH)        /* 16512 */
#define CTH_FLOATS (64 * CTH_PITCH)       /* 8320  */
#define SMEM_FLOATS (XS_FLOATS + CTH_FLOATS)
#define SMEM_BYTES (SMEM_FLOATS * 4)      /* 99328 B */

__global__ __launch_bounds__(256, 2)
void assign_kernel(const float* __restrict__ x) {
    extern __shared__ float sm[];
    float* Xs  = sm;                       // [128 pts][XS_PITCH]
    float* CtH = sm + XS_FLOATS;           // [64 d][CTH_PITCH]

    const int tid = threadIdx.x;
    const int tx = tid & 15;
    const int ty = tid >> 4;
    const int pBase = blockIdx.x * 128;

    // Load X tile: row-major [point][d], coalesced float4 global reads.
    {
        const int r0 = tid >> 5, lane = tid & 31;
        #pragma unroll
        for (int s = 0; s < 16; s++) {
            const int p = r0 + s * 8;
            float4 v = *(const float4*)(x + (size_t)(pBase + p) * D + lane * 4);
            float* dst = Xs + p * XS_PITCH + lane * 4;
            dst[0] = v.x; dst[1] = v.y; dst[2] = v.z; dst[3] = v.w;
        }
    }

    float xs[8];
    float bestv[8];
    int   besti[8];
    #pragma unroll
    for (int i = 0; i < 8; i++) {
        xs[i] = g_xsq[pBase + i * 16 + ty];
        bestv[i] = 3.4e38f;
        besti[i] = 0;
    }

    for (int chunk = 0; chunk < 8; chunk++) {
        const int c0 = chunk * 128;

        unsigned long long acc[8][4];
        #pragma unroll
        for (int i = 0; i < 8; i++)
            #pragma unroll
            for (int j = 0; j < 4; j++) acc[i][j] = 0ull;

        #pragma unroll
        for (int half = 0; half < 2; half++) {
            const int h0 = half * 64;
            __syncthreads();  // protect CtH before overwrite
            // Load centroid half-chunk TRANSPOSED: CtH[d][cent], d in [h0, h0+64)
            {
                const int w = tid >> 5, lane = tid & 31;
                const int cl = lane >> 4;        // 0..1
                const int d4 = lane & 15;        // float4 group along d
                #pragma unroll
                for (int s = 0; s < 8; s++) {
                    const int c = w * 2 + cl + s * 16;
                    float4 v = *(const float4*)(g_centroids +
                                 (size_t)(c0 + c) * D + h0 + d4 * 4);
                    CtH[(d4 * 4 + 0) * CTH_PITCH + c] = v.x;
                    CtH[(d4 * 4 + 1) * CTH_PITCH + c] = v.y;
                    CtH[(d4 * 4 + 2) * CTH_PITCH + c] = v.z;
                    CtH[(d4 * 4 + 3) * CTH_PITCH + c] = v.w;
                }
            }
            __syncthreads();

            #pragma unroll 4
            for (int d = 0; d < 64; d++) {
                const int dd = h0 + d;
                unsigned long long b2[4];
                const float* crow = CtH + d * CTH_PITCH + tx * 2;
                #pragma unroll
                for (int j = 0; j < 4; j++)
                    b2[j] = *(const unsigned long long*)(crow + j * 32);
                #pragma unroll
                for (int i = 0; i < 8; i++) {
                    const float av = Xs[(i * 16 + ty) * XS_PITCH + dd];
                    unsigned long long a2;
                    asm("mov.b64 %0, {%1, %1};" : "=l"(a2) : "f"(av));
                    #pragma unroll
                    for (int j = 0; j < 4; j++)
                        asm("fma.rn.f32x2 %0, %1, %2, %0;"
                            : "+l"(acc[i][j]) : "l"(a2), "l"(b2[j]));
                }
            }
        }

        // Epilogue: d = xsq - 2*dot + csq ; running argmin (ascending c per thread)
        float cs0[4], cs1[4];
        int   cb[4];
        #pragma unroll
        for (int j = 0; j < 4; j++) {
            const int c = c0 + j * 32 + tx * 2;
            cb[j] = c;
            cs0[j] = g_csq[c];
            cs1[j] = g_csq[c + 1];
        }
        #pragma unroll
        for (int i = 0; i < 8; i++) {
            #pragma unroll
            for (int j = 0; j < 4; j++) {
                float v0, v1;
                asm("mov.b64 {%0, %1}, %2;" : "=f"(v0), "=f"(v1) : "l"(acc[i][j]));
                const float d0 = fmaf(-2.f, v0, xs[i]) + cs0[j];
                const float d1 = fmaf(-2.f, v1, xs[i]) + cs1[j];
                if (d0 < bestv[i]) { bestv[i] = d0; besti[i] = cb[j]; }
                if (d1 < bestv[i]) { bestv[i] = d1; besti[i] = cb[j] + 1; }
            }
        }
    }

    // Cross-thread argmin reduction over the 16 tx lanes per point (lex order).
    __syncthreads();
    float* rv = sm;                         // [128][16] floats
    int*   ri = (int*)(sm + 128 * 16);      // [128][16] ints
    #pragma unroll
    for (int i = 0; i < 8; i++) {
        const int p = i * 16 + ty;
        rv[p * 16 + tx] = bestv[i];
        ri[p * 16 + tx] = besti[i];
    }
    __syncthreads();
    if (tid < 128) {
        float bv = rv[tid * 16];
        int   bi = ri[tid * 16];
        #pragma unroll
        for (int t = 1; t < 16; t++) {
            const float v = rv[tid * 16 + t];
            const int  ix = ri[tid * 16 + t];
            if (v < bv || (v == bv && ix < bi)) { bv = v; bi = ix; }
        }
        g_assign[pBase + tid] = bi;
    }
}

// ---------------- deterministic stable counting-sort of points by cluster ----------------
__global__ __launch_bounds__(256)
void rank_kernel() {
    __shared__ int hist[8][K];
    const int warp = threadIdx.x >> 5;
    const int lane = threadIdx.x & 31;
    const int chunk = blockIdx.x * 8 + warp;
    int* h = hist[warp];
    for (int i = lane; i < K; i += 32) h[i] = 0;
    __syncwarp();
    const int base_n = chunk * CHUNK;
    for (int g = 0; g < CHUNK / 32; g++) {
        const int n = base_n + g * 32 + lane;
        const int a = g_assign[n];
        const unsigned mask = __match_any_sync(0xffffffffu, a);
        const int before = __popc(mask & ((1u << lane) - 1u));
        const int b = h[a];
        __syncwarp();
        g_rank[n] = b + before;
        if (lane == (int)(__ffs(mask) - 1)) h[a] = b + __popc(mask);
        __syncwarp();
    }
    for (int i = lane; i < K; i += 32) g_hist[chunk * K + i] = h[i];
}

__global__ void chunkscan_kernel() {
    const int k = blockIdx.x * blockDim.x + threadIdx.x;  // 0..K-1
    if (k >= K) return;
    int run = 0;
    for (int c = 0; c < CHUNKS; c++) {
        const int t = g_hist[c * K + k];
        g_hist[c * K + k] = run;
        run += t;
    }
    g_counts_i[k] = run;
}

__global__ void offs_kernel() {
    __shared__ int s[K];
    const int k = threadIdx.x;
    const int my = g_counts_i[k];
    s[k] = my;
    __syncthreads();
    for (int o = 1; o < K; o <<= 1) {
        const int t = (k >= o) ? s[k - o] : 0;
        __syncthreads();
        s[k] += t;
        __syncthreads();
    }
    g_offs[k] = s[k] - my;
}

__global__ void scatter_kernel() {
    const int n = blockIdx.x * blockDim.x + threadIdx.x;
    if (n >= N) return;
    const int a = g_assign[n];
    const int chunk = n / CHUNK;
    const int slot = g_offs[a] + g_hist[chunk * K + a] + g_rank[n];
    g_order[slot] = n;
}

// Update: fp32 serial fold, ADJACENT-PAIR-SWAPPED ascending order (FROZEN —
// this exact order matched golden), then plain fp32 divide (0/0 -> NaN).
__global__ __launch_bounds__(128)
void update_kernel(const float* __restrict__ x) {
    const int k = blockIdx.x;
    const int d = threadIdx.x;
    const int cnt = g_counts_i[k];
    const int off = g_offs[k];
    float s = 0.f;
    for (int j = 0; j < cnt; j++) {
        int jj = j ^ 1;
        if (jj >= cnt) jj = j;          // odd tail element stays in place
        const int n = g_order[off + jj];
        s += x[(size_t)n * D + d];
    }
    g_centroids[k * D + d] = s / (float)cnt;
}

// ---------------- support kernels ----------------
__global__ void init_centroids_kernel(const float* __restrict__ x) {
    const int i = blockIdx.x * blockDim.x + threadIdx.x;
    if (i < K * D) g_centroids[i] = x[i];  // c0 = x[:K]
}

__global__ void xsq_kernel(const float* __restrict__ x) {
    const int gtid = blockIdx.x * blockDim.x + threadIdx.x;
    const int w = gtid >> 5;
    const int lane = gtid & 31;
    if (w < N) {
        float4 v = *(const float4*)(x + (size_t)w * D + lane * 4);
        float s = v.x * v.x + v.y * v.y + v.z * v.z + v.w * v.w;
        #pragma unroll
        for (int o = 16; o; o >>= 1) s += __shfl_down_sync(0xffffffffu, s, o);
        if (lane == 0) g_xsq[w] = s;
    }
}

// csq: serial fma chain (FROZEN — form used in the golden-matching run).
__global__ void csq_kernel() {
    const int k = blockIdx.x * blockDim.x + threadIdx.x;
    if (k < K) {
        const float* c = g_centroids + (size_t)k * D;
        float s = 0.f;
        #pragma unroll 8
        for (int d = 0; d < D; d++) s = fmaf(c[d], c[d], s);
        g_csq[k] = s;
    }
}

// Output (float32): [clusters(131072), centroids(131072), counts(1024)]
__global__ void writeout_kernel(float* __restrict__ out, int out_size) {
    const int i = blockIdx.x * blockDim.x + threadIdx.x;
    if (i >= out_size) return;
    if (i < N) {
        out[i] = (float)g_assign[i];
    } else if (i < N + K * D) {
        out[i] = g_centroids[i - N];
    } else if (i < N + K * D + K) {
        out[i] = (float)g_counts_i[i - N - K * D];
    }
}

// ---------------- launch ----------------
extern "C" void kernel_launch(void* const* d_in, const int* in_sizes, int n_in,
                              void* d_out, int out_size) {
    const float* x = (const float*)d_in[0];
    float* out = (float*)d_out;

    cudaFuncSetAttribute(assign_kernel,
                         cudaFuncAttributeMaxDynamicSharedMemorySize, SMEM_BYTES);

    init_centroids_kernel<<<(K * D + 255) / 256, 256>>>(x);
    xsq_kernel<<<(N * 32 + 255) / 256, 256>>>(x);
    csq_kernel<<<(K + 255) / 256, 256>>>();

    for (int it = 0; it < NITERS; it++) {
        assign_kernel<<<N / 128, 256, SMEM_BYTES>>>(x);
        rank_kernel<<<CHUNKS / 8, 256>>>();
        chunkscan_kernel<<<(K + 255) / 256, 256>>>();
        offs_kernel<<<1, K>>>();
        scatter_kernel<<<(N + 255) / 256, 256>>>();
        update_kernel<<<K, 128>>>(x);
        csq_kernel<<<(K + 255) / 256, 256>>>();
    }
    writeout_kernel<<<(out_size + 255) / 256, 256>>>(out, out_size);
}